// round 14
// baseline (speedup 1.0000x reference)
#include <cuda_runtime.h>
#include <math_constants.h>

// ============================================================================
// Chamfer loss: ONE persistent kernel, bucket-direct uniform grid (no sort).
// Phases: P1 bin -> gridbar -> P5 cell-major queries -> gridbar -> cleanup.
// P5: 4-lane group per cell; 9 neighbor counts loaded once per cell; queries
// processed in batches of 4 so each candidate load serves 4 distance tests.
// Exact: 3x3 always scanned; exit if best <= gb^2 (gb = per-axis
// min(cs+frac,2cs-frac) >= true margin); else ring-perimeter escape, rings >= r
// are >= (r-1)*cs away (fixed-bounds clamping only makes this conservative).
// Overflow (count > CAP): extras list is scanned by every query (candidates)
// and extra points get a scalar exact query (queries) -- exact regardless.
// ============================================================================

#define G      128
#define NCELL  (G * G)            // 16384 = 2^14
#define CAP    64
#define EMAX   16384
#define TPB    512
#define NW     (TPB / 32)
#define MAXBLK 256
#define FULL   0xFFFFFFFFu

#define X0F  (-6.5f)
#define Y0F  (-6.5f)
#define CSF  (0.1015625f)         // 13/128, exact in binary
#define INVF (9.846153846153847f) // 128/13
#define INFF CUDART_INF_F

__device__ int          g_arr;
__device__ volatile int g_gen;
__device__ int          g_task;
__device__ int          g_ecnt[2];
__device__ int          g_cnt[2 * NCELL];        // zero at load; self-cleaned
__device__ float2       g_bkt[2 * NCELL * CAP];  // 16.8 MB (L2-resident)
__device__ float2       g_ext[2][EMAX];

static __device__ __forceinline__ void gridbar(int nblk) {
    __syncthreads();
    if (threadIdx.x == 0) {
        __threadfence();
        int g = g_gen;
        if (atomicAdd(&g_arr, 1) == nblk - 1) {
            g_arr = 0;
            __threadfence();
            g_gen = g + 1;
        } else {
            while (g_gen == g) { }
        }
    }
    __syncthreads();
}

static __device__ __forceinline__ int cell_clamp(float v, float o) {
    return min(G - 1, max(0, (int)((v - o) * INVF)));
}

// Map perimeter index -> cell coords for Chebyshev ring r (r >= 1; 8r cells).
static __device__ __forceinline__ void ring_cell(int idx, int r, int cx, int cy,
                                                 int& xx, int& yy) {
    if (idx < 2 * r + 1)          { yy = cy - r; xx = cx - r + idx; }
    else if (idx < 4 * r + 2)     { yy = cy + r; xx = cx - r + (idx - (2 * r + 1)); }
    else { int k = idx - (4 * r + 2); yy = cy - r + 1 + (k >> 1);
           xx = (k & 1) ? cx + r : cx - r; }
}

// Scalar exact NN query (fallback for overflow points; dead at this size).
static __device__ float scalar_query(float2 Q, int ts, int net) {
    int cx = cell_clamp(Q.x, X0F), cy = cell_clamp(Q.y, Y0F);
    float best = INFF;
    for (int e = 0; e < net; e++) {
        float2 p = g_ext[ts][e];
        float dx = Q.x - p.x, dy = Q.y - p.y;
        best = fminf(best, fmaf(dx, dx, dy * dy));
    }
    for (int r = 0; r < 2 * G; r++) {
        if (r >= 2 && best < INFF) {
            float bb = (float)(r - 1) * CSF;
            if (bb * bb >= best) break;
        }
        if (r > 0 && cx - r < 0 && cx + r > G - 1 && cy - r < 0 && cy + r > G - 1)
            break;
        int per = (r == 0) ? 1 : 8 * r;
        for (int idx = 0; idx < per; idx++) {
            int xx = cx, yy = cy;
            if (r > 0) ring_cell(idx, r, cx, cy, xx, yy);
            if (xx < 0 || xx >= G || yy < 0 || yy >= G) continue;
            int cc = ts * NCELL + yy * G + xx;
            int n = min(g_cnt[cc], CAP), base = cc * CAP;
            for (int sl = 0; sl < n; sl++) {
                float2 p = g_bkt[base + sl];
                float dx = Q.x - p.x, dy = Q.y - p.y;
                best = fminf(best, fmaf(dx, dx, dy * dy));
            }
        }
    }
    return best;
}

// Group-cooperative exact escape from ring 2 (4 lanes split the perimeter).
static __device__ float escape4(float2 Q, int cx, int cy, int sub, int ts,
                                float best, unsigned gmask) {
    for (int r = 2; r < 2 * G; r++) {
        if (best < INFF) {
            float bb = (float)(r - 1) * CSF;
            if (bb * bb >= best) break;
        }
        if (cx - r < 0 && cx + r > G - 1 && cy - r < 0 && cy + r > G - 1) break;
        int per = 8 * r;
        for (int idx = sub; idx < per; idx += 4) {
            int xx, yy;
            ring_cell(idx, r, cx, cy, xx, yy);
            if (xx < 0 || xx >= G || yy < 0 || yy >= G) continue;
            int cc = ts * NCELL + yy * G + xx;
            int n = min(g_cnt[cc], CAP), base = cc * CAP;
            for (int sl = 0; sl < n; sl++) {
                float2 p = g_bkt[base + sl];
                float dx = Q.x - p.x, dy = Q.y - p.y;
                best = fminf(best, fmaf(dx, dx, dy * dy));
            }
        }
        best = fminf(best, __shfl_xor_sync(gmask, best, 1));
        best = fminf(best, __shfl_xor_sync(gmask, best, 2));
    }
    return best;
}

// ---------------------------------------------------------------------------
__global__ __launch_bounds__(TPB) void chamfer_fused(
    const float* __restrict__ A, int na,
    const float* __restrict__ B, int nb,
    float* __restrict__ out, int nblk)
{
    const int tid  = threadIdx.x;
    const int gsz  = nblk * TPB;
    const int gtid = blockIdx.x * TPB + tid;
    const int total = na + nb;

    // ---------------- P1: bin into buckets ----------------
    if (gtid == 0) { out[0] = 0.0f; g_task = 0; }
    for (int i = gtid; i < total; i += gsz) {
        const float2 p = (i < na) ? ((const float2*)A)[i]
                                  : ((const float2*)B)[i - na];
        int s = (i < na) ? 0 : 1;
        int c = s * NCELL + cell_clamp(p.y, Y0F) * G + cell_clamp(p.x, X0F);
        int pos = atomicAdd(&g_cnt[c], 1);
        if (pos < CAP) {
            g_bkt[c * CAP + pos] = p;
        } else {
            int e = atomicAdd(&g_ecnt[s], 1);
            if (e < EMAX) g_ext[s][e] = p;
        }
    }
    gridbar(nblk);

    // ---------------- P5: cell-major queries ----------------
    float acc = 0.0f;
    const int lane = tid & 31;
    const int sub  = lane & 3;
    const int grp  = lane >> 2;
    const unsigned gmask = 0xFu << (lane & 28);
    const int ne0 = min(g_ecnt[0], EMAX);
    const int ne1 = min(g_ecnt[1], EMAX);
    const int ntask = 2 * NCELL;              // divisible by 8

    for (;;) {
        int chunk;
        if (lane == 0) chunk = atomicAdd(&g_task, 8);
        chunk = __shfl_sync(FULL, chunk, 0);
        if (chunk >= ntask) break;

        int t  = chunk + grp;
        int s  = (t >= NCELL) ? 1 : 0;
        int ci = t - s * NCELL;
        int c  = (ci * 24593) & (NCELL - 1);  // odd mult: bijection mod 2^14
        int qbase = s * NCELL + c;
        int qn = min(g_cnt[qbase], CAP);
        if (qn == 0) continue;                // group-uniform

        int ts = s ^ 1;
        int cy = c >> 7, cx = c & (G - 1);
        int net = ts ? ne1 : ne0;

        // neighborhood: 9 counts/bases loaded ONCE per cell
        int tc[9], tb[9];
#pragma unroll
        for (int j = 0; j < 9; j++) {
            int yy = cy - 1 + j / 3, xx = cx - 1 + j % 3;
            bool ok = ((unsigned)yy < (unsigned)G) && ((unsigned)xx < (unsigned)G);
            int cc = ts * NCELL + yy * G + xx;
            tc[j] = ok ? min(g_cnt[cc], CAP) : 0;
            tb[j] = cc * CAP;
        }

        for (int qb = 0; qb < qn; qb += 4) {
            int m = min(4, qn - qb);
            float2 Q0 = g_bkt[qbase * CAP + qb];
            float2 Q1 = g_bkt[qbase * CAP + qb + min(1, m - 1)];
            float2 Q2 = g_bkt[qbase * CAP + qb + min(2, m - 1)];
            float2 Q3 = g_bkt[qbase * CAP + qb + min(3, m - 1)];
            float b0 = INFF, b1 = INFF, b2 = INFF, b3 = INFF;

#pragma unroll
            for (int j = 0; j < 9; j++) {
                for (int sl = sub; sl < tc[j]; sl += 4) {
                    float2 p = g_bkt[tb[j] + sl];
                    float dx, dy;
                    dx = Q0.x - p.x; dy = Q0.y - p.y; b0 = fminf(b0, fmaf(dx, dx, dy * dy));
                    dx = Q1.x - p.x; dy = Q1.y - p.y; b1 = fminf(b1, fmaf(dx, dx, dy * dy));
                    dx = Q2.x - p.x; dy = Q2.y - p.y; b2 = fminf(b2, fmaf(dx, dx, dy * dy));
                    dx = Q3.x - p.x; dy = Q3.y - p.y; b3 = fminf(b3, fmaf(dx, dx, dy * dy));
                }
            }
            for (int e = sub; e < net; e += 4) {   // extras as candidates
                float2 p = g_ext[ts][e];
                float dx, dy;
                dx = Q0.x - p.x; dy = Q0.y - p.y; b0 = fminf(b0, fmaf(dx, dx, dy * dy));
                dx = Q1.x - p.x; dy = Q1.y - p.y; b1 = fminf(b1, fmaf(dx, dx, dy * dy));
                dx = Q2.x - p.x; dy = Q2.y - p.y; b2 = fminf(b2, fmaf(dx, dx, dy * dy));
                dx = Q3.x - p.x; dy = Q3.y - p.y; b3 = fminf(b3, fmaf(dx, dx, dy * dy));
            }

            b0 = fminf(b0, __shfl_xor_sync(gmask, b0, 1));
            b0 = fminf(b0, __shfl_xor_sync(gmask, b0, 2));
            b1 = fminf(b1, __shfl_xor_sync(gmask, b1, 1));
            b1 = fminf(b1, __shfl_xor_sync(gmask, b1, 2));
            b2 = fminf(b2, __shfl_xor_sync(gmask, b2, 1));
            b2 = fminf(b2, __shfl_xor_sync(gmask, b2, 2));
            b3 = fminf(b3, __shfl_xor_sync(gmask, b3, 1));
            b3 = fminf(b3, __shfl_xor_sync(gmask, b3, 2));

            // exit bounds (query's own cell = processing cell) + escapes
            float fx, fy, gb;
            fx = (Q0.x - X0F) - (float)cx * CSF; fy = (Q0.y - Y0F) - (float)cy * CSF;
            gb = fmaxf(fminf(fminf(CSF + fx, 2.0f * CSF - fx),
                             fminf(CSF + fy, 2.0f * CSF - fy)), 0.0f);
            if (!(b0 <= gb * gb)) b0 = escape4(Q0, cx, cy, sub, ts, b0, gmask);
            if (m > 1) {
                fx = (Q1.x - X0F) - (float)cx * CSF; fy = (Q1.y - Y0F) - (float)cy * CSF;
                gb = fmaxf(fminf(fminf(CSF + fx, 2.0f * CSF - fx),
                                 fminf(CSF + fy, 2.0f * CSF - fy)), 0.0f);
                if (!(b1 <= gb * gb)) b1 = escape4(Q1, cx, cy, sub, ts, b1, gmask);
            }
            if (m > 2) {
                fx = (Q2.x - X0F) - (float)cx * CSF; fy = (Q2.y - Y0F) - (float)cy * CSF;
                gb = fmaxf(fminf(fminf(CSF + fx, 2.0f * CSF - fx),
                                 fminf(CSF + fy, 2.0f * CSF - fy)), 0.0f);
                if (!(b2 <= gb * gb)) b2 = escape4(Q2, cx, cy, sub, ts, b2, gmask);
            }
            if (m > 3) {
                fx = (Q3.x - X0F) - (float)cx * CSF; fy = (Q3.y - Y0F) - (float)cy * CSF;
                gb = fmaxf(fminf(fminf(CSF + fx, 2.0f * CSF - fx),
                                 fminf(CSF + fy, 2.0f * CSF - fy)), 0.0f);
                if (!(b3 <= gb * gb)) b3 = escape4(Q3, cx, cy, sub, ts, b3, gmask);
            }

            if (sub == 0)          acc += sqrtf(b0);
            if (sub == 1 && m > 1) acc += sqrtf(b1);
            if (sub == 2 && m > 2) acc += sqrtf(b2);
            if (sub == 3 && m > 3) acc += sqrtf(b3);
        }
    }

    // extras as queries (exact scalar path; dead at this size)
    {
        int netot = min(g_ecnt[0], EMAX) + min(g_ecnt[1], EMAX);
        int nq0 = min(g_ecnt[0], EMAX);
        for (int i2 = gtid; i2 < netot; i2 += gsz) {
            int s2 = (i2 >= nq0) ? 1 : 0;
            float2 Q = g_ext[s2][i2 - (s2 ? nq0 : 0)];
            int ts2 = s2 ^ 1;
            float bq = scalar_query(Q, ts2, min(g_ecnt[ts2], EMAX));
            acc += sqrtf(bq);
        }
    }

    // Block sum -> one atomicAdd per block.
#pragma unroll
    for (int o = 16; o > 0; o >>= 1)
        acc += __shfl_down_sync(FULL, acc, o);
    {
        __shared__ float ws[NW];
        int w = tid >> 5;
        if (lane == 0) ws[w] = acc;
        __syncthreads();
        if (w == 0) {
            acc = (lane < NW) ? ws[lane] : 0.0f;
#pragma unroll
            for (int o = 16; o > 0; o >>= 1)
                acc += __shfl_down_sync(FULL, acc, o);
            if (lane == 0) atomicAdd(out, acc);
        }
    }

    // ---------------- cleanup (post-barrier: all reads done) ----------------
    gridbar(nblk);
    for (int i = gtid; i < 2 * NCELL; i += gsz) g_cnt[i] = 0;
    if (gtid == 0) { g_ecnt[0] = 0; g_ecnt[1] = 0; }
}

// ---------------------------------------------------------------------------
extern "C" void kernel_launch(void* const* d_in, const int* in_sizes, int n_in,
                              void* d_out, int out_size) {
    const float* A = (const float*)d_in[0];
    const float* B = (const float*)d_in[1];
    int na = in_sizes[0] / 2;
    int nb = in_sizes[1] / 2;
    float* out = (float*)d_out;

    int sms = 0;
    if (cudaDeviceGetAttribute(&sms, cudaDevAttrMultiProcessorCount, 0) != cudaSuccess
        || sms <= 0) sms = 148;
    int nblk = sms;
    if (nblk > MAXBLK) nblk = MAXBLK;

    chamfer_fused<<<nblk, TPB>>>(A, na, B, nb, out, nblk);
}

// round 15
// speedup vs baseline: 1.4784x; 1.4784x over previous
#include <cuda_runtime.h>
#include <math_constants.h>

// ============================================================================
// Chamfer loss: ONE persistent kernel, exact uniform-grid NN, CSR layout.
// Base = R13 (41.5us-class). R15 deltas (only):
//  1. Merged scan: row-aligned block ownership + per-set atomic base cursors
//     (set0 from 0, set1 from na -> g_pts stays set-segregated). 3 barriers.
//     Padded row stride GP=132 (16B-aligned rows; pad offsets = row ends).
//  2. Escape initial W from current best (W*cs >= sqrt(best)+cs, so the
//     widen-rescan never fires from this choice); W=12 only when best=INF.
// P5 unchanged: dynamic 32-task warp chunks, 4 lanes/query, 6-offset
// prefetch, position-based exact exit bound gb.
// Exactness: 3x3 margin gb = per-axis min(cs+frac,2cs-frac); escape rows at
// |dy| have gap >= (dy-1)*cs; width exact when (W*cs)^2 >= best.
// Fixed bounds [-6.5,6.5]: clamped points are farther than their cell implies.
// ============================================================================

#define G      128
#define GP     132                    // padded row stride (16B-aligned rows)
#define NROWS  (2 * G)
#define PCELL  (G * GP)
#define TCP    (2 * PCELL)
#define TMAX   65536
#define TPB    512
#define NW     (TPB / 32)
#define MAXBLK 256
#define FULL   0xFFFFFFFFu

#define X0F  (-6.5f)
#define Y0F  (-6.5f)
#define CSF  (0.1015625f)              // 13/128, exact in binary
#define INVF (9.846153846153847f)      // 128/13

__device__ int          g_arr;
__device__ volatile int g_gen;
__device__ int          g_task;
__device__ int          g_cur[2];      // per-set base cursors
__device__ int          g_cnt[TCP];    // zero at load; self-cleaned each run
__device__ int          g_off[TCP];
__device__ int          g_cid[TMAX];   // fallback path only
__device__ int          g_rank[TMAX];  // fallback path only
__device__ float2       g_pts[TMAX];

static __device__ __forceinline__ void gridbar(int nblk) {
    __syncthreads();
    if (threadIdx.x == 0) {
        __threadfence();
        int g = g_gen;
        if (atomicAdd(&g_arr, 1) == nblk - 1) {
            g_arr = 0;
            __threadfence();
            g_gen = g + 1;
        } else {
            while (g_gen == g) { }
        }
    }
    __syncthreads();
}

// Block-wide exclusive scan; warp-uniform shfls, full masks.
static __device__ __forceinline__ int block_excl_scan(int v, int tid,
                                                      int* s_warp, int* total) {
    int lane = tid & 31, w = tid >> 5;
    int x = v;
#pragma unroll
    for (int o = 1; o < 32; o <<= 1) {
        int y = __shfl_up_sync(FULL, x, o);
        if (lane >= o) x += y;
    }
    if (lane == 31) s_warp[w] = x;
    __syncthreads();
    if (w == 0) {
        int y = (lane < NW) ? s_warp[lane] : 0;
#pragma unroll
        for (int o = 1; o < NW; o <<= 1) {
            int z = __shfl_up_sync(FULL, y, o);
            if (lane >= o) y += z;
        }
        if (lane < NW) s_warp[lane] = y;
    }
    __syncthreads();
    int base = w ? s_warp[w - 1] : 0;
    *total = s_warp[NW - 1];
    __syncthreads();
    return base + x - v;
}

static __device__ __forceinline__ int cell_clamp(float v, float o) {
    return min(G - 1, max(0, (int)((v - o) * INVF)));
}

// ---------------------------------------------------------------------------
__global__ __launch_bounds__(TPB) void chamfer_fused(
    const float* __restrict__ A, int na,
    const float* __restrict__ B, int nb,
    float* __restrict__ out, int nblk)
{
    const int tid  = threadIdx.x;
    const int b    = blockIdx.x;
    const int gsz  = nblk * TPB;
    const int gtid = b * TPB + tid;
    const int total = na + nb;

    __shared__ int s_warp[NW];
    __shared__ int s_base;

    // ---------------- P1: bin (g_cnt zero from load / previous self-clean) ----
    if (gtid == 0) {
        out[0] = 0.0f; g_task = 0;
        g_cur[0] = 0; g_cur[1] = na;   // set-segregated bases
    }

    // Register-carried point: each thread owns <= 1 point at this size.
    float2 myp = make_float2(0.0f, 0.0f);
    int myc = -1, myrank = 0;
    if (gtid < total) {
        myp = (gtid < na) ? ((const float2*)A)[gtid]
                          : ((const float2*)B)[gtid - na];
        int s = (gtid < na) ? 0 : 1;
        myc = s * PCELL + cell_clamp(myp.y, Y0F) * GP + cell_clamp(myp.x, X0F);
        myrank = atomicAdd(&g_cnt[myc], 1);
    }
    // Fallback (total > gsz): memory-carried, not hit at this problem size.
    for (int i = gtid + gsz; i < total; i += gsz) {
        const float2 p = (i < na) ? ((const float2*)A)[i]
                                  : ((const float2*)B)[i - na];
        int s = (i < na) ? 0 : 1;
        int c = s * PCELL + cell_clamp(p.y, Y0F) * GP + cell_clamp(p.x, X0F);
        g_cid[i]  = c;
        g_rank[i] = atomicAdd(&g_cnt[c], 1);
    }
    gridbar(nblk);

    // ---------------- P2: row-aligned scan + per-set atomic base -------------
    // Block b owns rows [b*rpb, b*rpb+rpb). rpb=2 divides G, so a block's rows
    // never straddle the set boundary. Pad entries (x >= G) scan to row end.
    const int rpb   = (NROWS + nblk - 1) / nblk;   // 2 @ nblk in [128,256]
    const int row0  = b * rpb;
    const int nrow  = max(0, min(NROWS - row0, rpb));
    const int ncell = nrow * GP;                   // <= 264 <= TPB
    const int cbeg  = row0 * GP;
    int v = (tid < ncell) ? g_cnt[cbeg + tid] : 0;
    if (tid < ncell) g_cnt[cbeg + tid] = 0;        // self-clean for next run
    int btot;
    int excl = block_excl_scan(v, tid, s_warp, &btot);
    if (tid == 0 && nrow > 0)
        s_base = atomicAdd(&g_cur[row0 >= G ? 1 : 0], btot);
    __syncthreads();
    if (tid < ncell) g_off[cbeg + tid] = s_base + excl;
    gridbar(nblk);

    // ---------------- P4: scatter fill (register-carried fast path) ----------
    if (myc >= 0) g_pts[g_off[myc] + myrank] = myp;
    for (int i = gtid + gsz; i < total; i += gsz) {
        const float2 p = (i < na) ? ((const float2*)A)[i]
                                  : ((const float2*)B)[i - na];
        g_pts[g_off[g_cid[i]] + g_rank[i]] = p;
    }
    gridbar(nblk);

    // ---------------- P5: query (4 lanes/query; dynamic warp chunks) ---------
    float acc = 0.0f;
    const int ntask = 4 * total;              // multiple of 4
    const int lane  = tid & 31;
    const unsigned gmask = 0xFu << (lane & 28);
    const float INF = CUDART_INF_F;

    for (;;) {
        int chunk;
        if (lane == 0) chunk = atomicAdd(&g_task, 32);
        chunk = __shfl_sync(FULL, chunk, 0);
        if (chunk >= ntask) break;

        int task = chunk + lane;
        bool valid = task < ntask;
        if (!valid) task = ntask - 1;         // clamped lanes: complete group, discarded
        int q   = task >> 2;
        int sub = task & 3;
        float2 Q = g_pts[q];                  // set-segregated: [0,na) = set 0
        int cx = cell_clamp(Q.x, X0F);
        int cy = cell_clamp(Q.y, Y0F);
        const int* __restrict__ off = g_off + ((q < na) ? PCELL : 0);

        float best = INF;

        // fast path: 3x3; all 6 row-offsets prefetched (independent loads).
        {
            int xlo = max(cx - 1, 0), xhi = min(cx + 1, G - 1);
            int sg[3], eg[3];
#pragma unroll
            for (int j = 0; j < 3; j++) {
                int yy = min(max(cy - 1 + j, 0), G - 1);
                sg[j] = off[yy * GP + xlo];
                eg[j] = off[yy * GP + xhi + 1];
            }
#pragma unroll
            for (int j = 0; j < 3; j++)
                for (int k = sg[j] + sub; k < eg[j]; k += 4) {
                    float2 p = g_pts[k];
                    float dx = Q.x - p.x, dy = Q.y - p.y;
                    best = fminf(best, fmaf(dx, dx, dy * dy));
                }
        }
        best = fminf(best, __shfl_xor_sync(gmask, best, 1));
        best = fminf(best, __shfl_xor_sync(gmask, best, 2));

        // exact exit bound from true position in cell (conservative for any f)
        float fx = (Q.x - X0F) - (float)cx * CSF;
        float fy = (Q.y - Y0F) - (float)cy * CSF;
        float gb = fminf(fminf(CSF + fx, 2.0f * CSF - fx),
                         fminf(CSF + fy, 2.0f * CSF - fy));
        gb = fmaxf(gb, 0.0f);

        // escape: row-band scan (group-uniform control flow)
        if (!(best <= gb * gb)) {
            // initial width from known best: W*cs >= sqrt(best)+cs, so the
            // width-sufficiency check passes on first pass (best only shrinks)
            int W = (best < INF) ? ((int)(sqrtf(best) * INVF) + 2) : 12;
            for (;;) {
                if (best < INF) {
                    int Wn = (int)(sqrtf(best) * INVF) + 2;
                    if (Wn > W) W = Wn;
                }
                if (W > G - 1) W = G - 1;
                int xlo = max(cx - W, 0), xhi = min(cx + W, G - 1);

                for (int dy = 0; dy < G; dy++) {
                    if (dy >= 1 && best < INF) {
                        float bb = (float)(dy - 1) * CSF;
                        if (bb * bb >= best) break;
                    }
                    int yt = cy - dy, yb = cy + dy;
                    if (yt < 0 && yb > G - 1) break;
                    if (yt >= 0) {
                        int s0 = off[yt * GP + xlo], e0 = off[yt * GP + xhi + 1];
                        for (int k = s0 + sub; k < e0; k += 4) {
                            float2 p = g_pts[k];
                            float dx = Q.x - p.x, dyv = Q.y - p.y;
                            best = fminf(best, fmaf(dx, dx, dyv * dyv));
                        }
                    }
                    if (dy > 0 && yb <= G - 1) {
                        int s0 = off[yb * GP + xlo], e0 = off[yb * GP + xhi + 1];
                        for (int k = s0 + sub; k < e0; k += 4) {
                            float2 p = g_pts[k];
                            float dx = Q.x - p.x, dyv = Q.y - p.y;
                            best = fminf(best, fmaf(dx, dx, dyv * dyv));
                        }
                    }
                    best = fminf(best, __shfl_xor_sync(gmask, best, 1));
                    best = fminf(best, __shfl_xor_sync(gmask, best, 2));
                }

                bool fullwidth = (xlo == 0 && xhi == G - 1);
                if (best < INF) {
                    float wb = (float)W * CSF;
                    if (wb * wb >= best || fullwidth) break;
                } else if (fullwidth) {
                    break;
                }
                W <<= 1;
            }
        }

        if (sub == 0 && valid) acc += sqrtf(best);
    }

    // Block sum -> one atomicAdd per block.
#pragma unroll
    for (int o = 16; o > 0; o >>= 1)
        acc += __shfl_down_sync(FULL, acc, o);
    {
        __shared__ float ws[NW];
        int w = tid >> 5;
        if (lane == 0) ws[w] = acc;
        __syncthreads();
        if (w == 0) {
            acc = (lane < NW) ? ws[lane] : 0.0f;
#pragma unroll
            for (int o = 16; o > 0; o >>= 1)
                acc += __shfl_down_sync(FULL, acc, o);
            if (lane == 0) atomicAdd(out, acc);
        }
    }
}

// ---------------------------------------------------------------------------
extern "C" void kernel_launch(void* const* d_in, const int* in_sizes, int n_in,
                              void* d_out, int out_size) {
    const float* A = (const float*)d_in[0];
    const float* B = (const float*)d_in[1];
    int na = in_sizes[0] / 2;
    int nb = in_sizes[1] / 2;
    float* out = (float*)d_out;

    int sms = 0;
    if (cudaDeviceGetAttribute(&sms, cudaDevAttrMultiProcessorCount, 0) != cudaSuccess
        || sms <= 0) sms = 148;
    int nblk = sms;
    if (nblk > MAXBLK) nblk = MAXBLK;
    if (nblk < 128)    nblk = 128;     // rpb=2 (divides G): no set straddle
    chamfer_fused<<<nblk, TPB>>>(A, na, B, nb, out, nblk);
}